// round 1
// baseline (speedup 1.0000x reference)
#include <cuda_runtime.h>
#include <cuda_bf16.h>
#include <math.h>

// ---------------------------------------------------------------------------
// Problem constants
// ---------------------------------------------------------------------------
#define BATCH     4
#define SEQLEN    1024
#define VOCAB     28
#define D_MODEL   1024
#define N_LAYERS  4
#define D_INNER   2048
#define D_STATE   16
#define DT_RANK   64
#define D_CONV    4
#define NUM_CLS   2
#define ROWS      (BATCH * SEQLEN)          // 4096

// ---------------------------------------------------------------------------
// Scratch buffers (device globals; no runtime allocation allowed)
// ---------------------------------------------------------------------------
__device__ float g_h    [ROWS * D_MODEL];        // residual stream        16 MB
__device__ float g_xn   [ROWS * D_MODEL];        // rmsnorm out / dec tmp  16 MB
__device__ float g_xz   [ROWS * 2 * D_INNER];    // in_proj out            64 MB
__device__ float g_xc   [ROWS * D_INNER];        // conv+silu out          32 MB
__device__ float g_dbc  [ROWS * (DT_RANK + 2*D_STATE)]; // x_proj out      1.5 MB
__device__ float g_delta[ROWS * D_INNER];        // softplus(dt)           32 MB
__device__ float g_y    [ROWS * D_INNER];        // scan out (gated)       32 MB

// ---------------------------------------------------------------------------
// Embedding + positional encoding
// ---------------------------------------------------------------------------
__global__ void embed_kernel(const int* __restrict__ x,
                             const float* __restrict__ emb,
                             const float* __restrict__ pos,
                             float* __restrict__ out)
{
    int idx = blockIdx.x * blockDim.x + threadIdx.x;           // over ROWS*D_MODEL
    if (idx >= ROWS * D_MODEL) return;
    int d = idx & (D_MODEL - 1);
    int r = idx >> 10;           // D_MODEL = 1024
    int l = r & (SEQLEN - 1);
    int tok = x[r];
    out[idx] = emb[tok * D_MODEL + d] + pos[l * D_MODEL + d];
}

// ---------------------------------------------------------------------------
// RMSNorm (one block per row)
// ---------------------------------------------------------------------------
__global__ void rmsnorm_kernel(const float* __restrict__ h,
                               const float* __restrict__ w,
                               float* __restrict__ out)
{
    int r = blockIdx.x;
    const float* row = h + (size_t)r * D_MODEL;
    int tid = threadIdx.x;

    float s = 0.f;
    #pragma unroll
    for (int i = tid; i < D_MODEL; i += 256) { float v = row[i]; s += v * v; }

    __shared__ float red[8];
    // warp reduce
    #pragma unroll
    for (int o = 16; o > 0; o >>= 1) s += __shfl_down_sync(0xffffffffu, s, o);
    if ((tid & 31) == 0) red[tid >> 5] = s;
    __syncthreads();
    __shared__ float scale;
    if (tid == 0) {
        float t = 0.f;
        #pragma unroll
        for (int i = 0; i < 8; i++) t += red[i];
        scale = rsqrtf(t * (1.0f / D_MODEL) + 1e-5f);
    }
    __syncthreads();
    float sc = scale;
    #pragma unroll
    for (int i = tid; i < D_MODEL; i += 256)
        out[(size_t)r * D_MODEL + i] = row[i] * sc * w[i];
}

// ---------------------------------------------------------------------------
// Generic NT GEMM: C[M,N] = A[M,K] (row-major, lda) * B[N,K]^T (row-major, ldb)
// Epilogue: 0 = store, 1 = C += v, 2 = relu(v+bias), 3 = v+bias, 4 = softplus(v+bias)
// ---------------------------------------------------------------------------
#define GBM 128
#define GBN 128
#define GBK 8

template <int EPI>
__global__ void __launch_bounds__(256, 2) gemm_nt(
    const float* __restrict__ A, int lda,
    const float* __restrict__ B, int ldb,
    float* __restrict__ C, int ldc,
    int M, int N, int K,
    const float* __restrict__ bias)
{
    __shared__ float As[GBK][GBM];
    __shared__ float Bs[GBK][GBN];

    int tid = threadIdx.x;
    int tx = tid & 15;
    int ty = tid >> 4;
    int bm = blockIdx.y * GBM;
    int bn = blockIdx.x * GBN;

    int lrow = tid >> 1;          // 0..127
    int lkc  = (tid & 1) * 4;     // 0 or 4

    float acc[8][8];
    #pragma unroll
    for (int i = 0; i < 8; i++)
        #pragma unroll
        for (int j = 0; j < 8; j++) acc[i][j] = 0.f;

    int nkt = (K + GBK - 1) / GBK;
    for (int kt = 0; kt < nkt; kt++) {
        int k0 = kt * GBK;
        // A tile
        {
            int gm = bm + lrow;
            float4 v = make_float4(0.f, 0.f, 0.f, 0.f);
            if (gm < M && (k0 + lkc + 3) < K)
                v = *(const float4*)(A + (size_t)gm * lda + k0 + lkc);
            As[lkc + 0][lrow] = v.x; As[lkc + 1][lrow] = v.y;
            As[lkc + 2][lrow] = v.z; As[lkc + 3][lrow] = v.w;
        }
        // B tile
        {
            int gn = bn + lrow;
            float4 v = make_float4(0.f, 0.f, 0.f, 0.f);
            if (gn < N && (k0 + lkc + 3) < K)
                v = *(const float4*)(B + (size_t)gn * ldb + k0 + lkc);
            Bs[lkc + 0][lrow] = v.x; Bs[lkc + 1][lrow] = v.y;
            Bs[lkc + 2][lrow] = v.z; Bs[lkc + 3][lrow] = v.w;
        }
        __syncthreads();

        #pragma unroll
        for (int k = 0; k < GBK; k++) {
            float4 a0 = *(const float4*)&As[k][ty * 4];
            float4 a1 = *(const float4*)&As[k][64 + ty * 4];
            float4 b0 = *(const float4*)&Bs[k][tx * 4];
            float4 b1 = *(const float4*)&Bs[k][64 + tx * 4];
            float av[8] = {a0.x, a0.y, a0.z, a0.w, a1.x, a1.y, a1.z, a1.w};
            float bv[8] = {b0.x, b0.y, b0.z, b0.w, b1.x, b1.y, b1.z, b1.w};
            #pragma unroll
            for (int i = 0; i < 8; i++)
                #pragma unroll
                for (int j = 0; j < 8; j++)
                    acc[i][j] = fmaf(av[i], bv[j], acc[i][j]);
        }
        __syncthreads();
    }

    #pragma unroll
    for (int i = 0; i < 8; i++) {
        int m = bm + ((i < 4) ? (ty * 4 + i) : (64 + ty * 4 + i - 4));
        if (m >= M) continue;
        #pragma unroll
        for (int j = 0; j < 8; j++) {
            int n = bn + ((j < 4) ? (tx * 4 + j) : (64 + tx * 4 + j - 4));
            if (n >= N) continue;
            float v = acc[i][j];
            size_t idx = (size_t)m * ldc + n;
            if (EPI == 0) {
                C[idx] = v;
            } else if (EPI == 1) {
                C[idx] += v;
            } else if (EPI == 2) {
                v += bias[n];
                C[idx] = v > 0.f ? v : 0.f;
            } else if (EPI == 3) {
                C[idx] = v + bias[n];
            } else {
                v += bias[n];
                C[idx] = (v > 20.f) ? v : log1pf(__expf(v));
            }
        }
    }
}

// ---------------------------------------------------------------------------
// Causal depthwise conv (width 4) + bias + SiLU.
// in:  g_xz[:, 0:D_INNER]  (row stride 2*D_INNER)
// out: g_xc (row stride D_INNER)
// ---------------------------------------------------------------------------
__global__ void conv_silu_kernel(const float* __restrict__ xz,
                                 const float* __restrict__ cw,
                                 const float* __restrict__ cb,
                                 float* __restrict__ xc)
{
    int idx = blockIdx.x * blockDim.x + threadIdx.x;   // over ROWS*D_INNER
    if (idx >= ROWS * D_INNER) return;
    int d = idx & (D_INNER - 1);
    int r = idx >> 11;                 // D_INNER = 2048
    int l = r & (SEQLEN - 1);
    int b = r >> 10;

    float w0 = cw[d * 4 + 0], w1 = cw[d * 4 + 1], w2 = cw[d * 4 + 2], w3 = cw[d * 4 + 3];
    size_t base = ((size_t)b * SEQLEN) * (2 * D_INNER) + d;
    float acc = cb[d];
    if (l >= 3) acc = fmaf(xz[base + (size_t)(l - 3) * (2 * D_INNER)], w0, acc);
    if (l >= 2) acc = fmaf(xz[base + (size_t)(l - 2) * (2 * D_INNER)], w1, acc);
    if (l >= 1) acc = fmaf(xz[base + (size_t)(l - 1) * (2 * D_INNER)], w2, acc);
    acc = fmaf(xz[base + (size_t)l * (2 * D_INNER)], w3, acc);
    // silu
    float s = acc / (1.f + __expf(-acc));
    xc[idx] = s;
}

// ---------------------------------------------------------------------------
// Selective scan. 16 lanes = 16 states per channel; 2 channels per warp.
// Fuses y = (scan + D*xc) * silu(z).
// ---------------------------------------------------------------------------
__global__ void scan_kernel(const float* __restrict__ delta,
                            const float* __restrict__ xc,
                            const float* __restrict__ dbc,
                            const float* __restrict__ xz,
                            const float* __restrict__ A_log,
                            const float* __restrict__ Dp,
                            float* __restrict__ yout)
{
    int gwarp = (blockIdx.x * blockDim.x + threadIdx.x) >> 5;
    int lane = threadIdx.x & 31;
    int n = lane & 15;
    int pair = gwarp * 2 + (lane >> 4);        // b * D_INNER + d
    int b = pair >> 11;
    int d = pair & (D_INNER - 1);
    if (b >= BATCH) return;

    float An = -__expf(A_log[d * D_STATE + n]);
    float Dv = Dp[d];
    float h = 0.f;

    size_t rbase = (size_t)b * SEQLEN;
    for (int l = 0; l < SEQLEN; l++) {
        size_t r = rbase + l;
        float dlt = delta[r * D_INNER + d];
        float xcv = xc[r * D_INNER + d];
        float Bv = dbc[r * 96 + DT_RANK + n];
        float Cv = dbc[r * 96 + DT_RANK + D_STATE + n];
        float dA = __expf(dlt * An);
        h = fmaf(dA, h, dlt * xcv * Bv);
        float y = h * Cv;
        y += __shfl_xor_sync(0xffffffffu, y, 1);
        y += __shfl_xor_sync(0xffffffffu, y, 2);
        y += __shfl_xor_sync(0xffffffffu, y, 4);
        y += __shfl_xor_sync(0xffffffffu, y, 8);
        if (n == 0) {
            float zv = xz[r * (2 * D_INNER) + D_INNER + d];
            float sz = zv / (1.f + __expf(-zv));
            yout[r * D_INNER + d] = (y + Dv * xcv) * sz;
        }
    }
}

// ---------------------------------------------------------------------------
// Classifier head on h[:, -1, :] (tiny: 4 rows)
// ---------------------------------------------------------------------------
__global__ void cls_kernel(const float* __restrict__ h,
                           const float* __restrict__ w1, const float* __restrict__ b1,
                           const float* __restrict__ w2, const float* __restrict__ b2,
                           float* __restrict__ out)
{
    __shared__ float sh[D_MODEL];
    __shared__ float t1[D_MODEL];
    __shared__ float red[256];
    int b = blockIdx.x, tid = threadIdx.x;
    const float* row = h + ((size_t)b * SEQLEN + (SEQLEN - 1)) * D_MODEL;
    for (int i = tid; i < D_MODEL; i += 256) sh[i] = row[i];
    __syncthreads();
    for (int e = tid; e < D_MODEL; e += 256) {
        const float* wr = w1 + (size_t)e * D_MODEL;
        float acc = b1[e];
        #pragma unroll 4
        for (int k = 0; k < D_MODEL; k += 4) {
            float4 w4 = *(const float4*)(wr + k);
            acc = fmaf(sh[k], w4.x, acc);
            acc = fmaf(sh[k + 1], w4.y, acc);
            acc = fmaf(sh[k + 2], w4.z, acc);
            acc = fmaf(sh[k + 3], w4.w, acc);
        }
        t1[e] = acc > 0.f ? acc : 0.f;
    }
    __syncthreads();
    for (int c = 0; c < NUM_CLS; c++) {
        float p = 0.f;
        for (int k = tid; k < D_MODEL; k += 256) p = fmaf(t1[k], w2[c * D_MODEL + k], p);
        red[tid] = p;
        __syncthreads();
        for (int s = 128; s > 0; s >>= 1) {
            if (tid < s) red[tid] += red[tid + s];
            __syncthreads();
        }
        if (tid == 0) out[b * NUM_CLS + c] = red[0] + b2[c];
        __syncthreads();
    }
}

// ---------------------------------------------------------------------------
// Launch
// ---------------------------------------------------------------------------
static inline dim3 gemm_grid(int M, int N)
{
    return dim3((N + GBN - 1) / GBN, (M + GBM - 1) / GBM);
}

extern "C" void kernel_launch(void* const* d_in, const int* in_sizes, int n_in,
                              void* d_out, int out_size)
{
    const int*   x_tok     = (const int*)d_in[0];
    const float* embedding = (const float*)d_in[1];
    const float* pos_enc   = (const float*)d_in[2];
    const float* norm_w    = (const float*)d_in[3];
    const float* in_proj_w = (const float*)d_in[4];
    const float* conv_w    = (const float*)d_in[5];
    const float* conv_b    = (const float*)d_in[6];
    const float* x_proj_w  = (const float*)d_in[7];
    const float* dt_proj_w = (const float*)d_in[8];
    const float* dt_proj_b = (const float*)d_in[9];
    const float* A_log     = (const float*)d_in[10];
    const float* Dp        = (const float*)d_in[11];
    const float* out_proj_w= (const float*)d_in[12];
    const float* cls_fc1_w = (const float*)d_in[13];
    const float* cls_fc1_b = (const float*)d_in[14];
    const float* cls_fc2_w = (const float*)d_in[15];
    const float* cls_fc2_b = (const float*)d_in[16];
    const float* dec_fc1_w = (const float*)d_in[17];
    const float* dec_fc1_b = (const float*)d_in[18];
    const float* dec_fc2_w = (const float*)d_in[19];
    const float* dec_fc2_b = (const float*)d_in[20];

    float *h, *xn, *xz, *xc, *dbc, *delta, *y;
    cudaGetSymbolAddress((void**)&h, g_h);
    cudaGetSymbolAddress((void**)&xn, g_xn);
    cudaGetSymbolAddress((void**)&xz, g_xz);
    cudaGetSymbolAddress((void**)&xc, g_xc);
    cudaGetSymbolAddress((void**)&dbc, g_dbc);
    cudaGetSymbolAddress((void**)&delta, g_delta);
    cudaGetSymbolAddress((void**)&y, g_y);

    float* out_dec = (float*)d_out;                       // (4,1024,28)
    float* out_cls = (float*)d_out + ROWS * VOCAB;        // (4,2)

    // Embedding + pos
    embed_kernel<<<(ROWS * D_MODEL + 255) / 256, 256>>>(x_tok, embedding, pos_enc, h);

    for (int l = 0; l < N_LAYERS; l++) {
        const float* inw = in_proj_w + (size_t)l * (2 * D_INNER) * D_MODEL;
        const float* cw  = conv_w   + (size_t)l * D_INNER * D_CONV;
        const float* cb  = conv_b   + (size_t)l * D_INNER;
        const float* xpw = x_proj_w + (size_t)l * 96 * D_INNER;
        const float* dtw = dt_proj_w+ (size_t)l * D_INNER * DT_RANK;
        const float* dtb = dt_proj_b+ (size_t)l * D_INNER;
        const float* al  = A_log    + (size_t)l * D_INNER * D_STATE;
        const float* dp  = Dp       + (size_t)l * D_INNER;
        const float* ow  = out_proj_w + (size_t)l * D_MODEL * D_INNER;
        const float* nw  = norm_w   + (size_t)l * D_MODEL;

        // 1. rmsnorm
        rmsnorm_kernel<<<ROWS, 256>>>(h, nw, xn);
        // 2. xz = xn @ in_proj_w^T
        gemm_nt<0><<<gemm_grid(ROWS, 2 * D_INNER), 256>>>(
            xn, D_MODEL, inw, D_MODEL, xz, 2 * D_INNER,
            ROWS, 2 * D_INNER, D_MODEL, nullptr);
        // 3. conv + silu
        conv_silu_kernel<<<(ROWS * D_INNER + 255) / 256, 256>>>(xz, cw, cb, xc);
        // 4. dbc = xc @ x_proj_w^T
        gemm_nt<0><<<gemm_grid(ROWS, 96), 256>>>(
            xc, D_INNER, xpw, D_INNER, dbc, 96,
            ROWS, 96, D_INNER, nullptr);
        // 5. delta = softplus(dbc[:, :64] @ dt_proj_w^T + dt_b)
        gemm_nt<4><<<gemm_grid(ROWS, D_INNER), 256>>>(
            dbc, 96, dtw, DT_RANK, delta, D_INNER,
            ROWS, D_INNER, DT_RANK, dtb);
        // 6. selective scan (+ gate)
        scan_kernel<<<(BATCH * D_INNER / 2 + 7) / 8, 256>>>(
            delta, xc, dbc, xz, al, dp, y);
        // 7. h += y @ out_proj_w^T
        gemm_nt<1><<<gemm_grid(ROWS, D_MODEL), 256>>>(
            y, D_INNER, ow, D_INNER, h, D_MODEL,
            ROWS, D_MODEL, D_INNER, nullptr);
    }

    // Decoder MLP: t = relu(h @ W1^T + b1); x_dec = t @ W2^T + b2
    gemm_nt<2><<<gemm_grid(ROWS, D_MODEL), 256>>>(
        h, D_MODEL, dec_fc1_w, D_MODEL, xn, D_MODEL,
        ROWS, D_MODEL, D_MODEL, dec_fc1_b);
    gemm_nt<3><<<gemm_grid(ROWS, VOCAB), 256>>>(
        xn, D_MODEL, dec_fc2_w, D_MODEL, out_dec, VOCAB,
        ROWS, VOCAB, D_MODEL, dec_fc2_b);

    // Classifier head
    cls_kernel<<<BATCH, 256>>>(h, cls_fc1_w, cls_fc1_b, cls_fc2_w, cls_fc2_b, out_cls);
}